// round 1
// baseline (speedup 1.0000x reference)
#include <cuda_runtime.h>
#include <math.h>

#define TTOK 4096
#define DHID 1024
#define NEXP 64
#define IMOE 512
#define NPAIR 8192

// ---------------- scratch (static device globals; no allocation) ----------------
__device__ int   g_cnt[NEXP];
__device__ int   g_off[NEXP + 1];
__device__ int   g_fill[NEXP];
__device__ int   g_pe[NPAIR];
__device__ float g_pw[NPAIR];
__device__ int   g_slot_tok[NPAIR];
__device__ float g_slot_w[NPAIR];
__device__ float g_shgate[TTOK];
__device__ float g_logits[TTOK * NEXP];
__device__ float g_h[NPAIR * 2 * IMOE];    // routed gate_up output [8192,1024]
__device__ float g_act[NPAIR * IMOE];      // routed activated    [8192,512]
__device__ float g_hg[TTOK * IMOE];        // shared gate         [4096,512]
__device__ float g_hu[TTOK * IMOE];        // shared up           [4096,512]
__device__ float g_acts[TTOK * IMOE];      // shared activated    [4096,512]

// ---------------- tiny kernels ----------------
__global__ void zero_kernel() {
    if (threadIdx.x < NEXP) g_cnt[threadIdx.x] = 0;
}

__global__ void scan_kernel() {
    if (threadIdx.x == 0) {
        int a = 0;
        for (int e = 0; e < NEXP; e++) { g_off[e] = a; g_fill[e] = a; a += g_cnt[e]; }
        g_off[NEXP] = a;
    }
}

__global__ void scatter_kernel() {
    int p = blockIdx.x * blockDim.x + threadIdx.x;
    if (p < NPAIR) {
        int e = g_pe[p];
        int s = atomicAdd(&g_fill[e], 1);
        g_slot_tok[s] = p >> 1;   // source token
        g_slot_w[s]   = g_pw[p];
    }
}

// softmax over 64 logits, top-2 select+normalize, shared-expert sigmoid gate.
// one warp per token, 8 tokens per 256-thread block.
__global__ void softmax_topk_kernel(const float* __restrict__ x,
                                    const float* __restrict__ sheg,
                                    float* __restrict__ probs_out) {
    int w = threadIdx.x >> 5, lane = threadIdx.x & 31;
    int t = blockIdx.x * 8 + w;
    if (t >= TTOK) return;

    // shared-expert gate: sigmoid(x[t] . sh_expert_gate_w)
    const float* xr = x + (size_t)t * DHID;
    float sd = 0.f;
    for (int k = lane; k < DHID; k += 32) sd += xr[k] * sheg[k];
    #pragma unroll
    for (int o = 16; o; o >>= 1) sd += __shfl_xor_sync(~0u, sd, o);
    if (lane == 0) g_shgate[t] = 1.f / (1.f + expf(-sd));

    float l0 = g_logits[t * 64 + lane];
    float l1 = g_logits[t * 64 + 32 + lane];
    float m = fmaxf(l0, l1);
    #pragma unroll
    for (int o = 16; o; o >>= 1) m = fmaxf(m, __shfl_xor_sync(~0u, m, o));
    float e0 = expf(l0 - m), e1 = expf(l1 - m);
    float s = e0 + e1;
    #pragma unroll
    for (int o = 16; o; o >>= 1) s += __shfl_xor_sync(~0u, s, o);
    float inv = 1.f / s;
    float p0 = e0 * inv, p1 = e1 * inv;
    if (probs_out) {
        probs_out[t * 64 + lane]      = p0;
        probs_out[t * 64 + 32 + lane] = p1;
    }
    // per-lane (top, second) of its two entries; tie -> lower index
    float v0, v1; int i0, i1;
    if (p1 > p0) { v0 = p1; i0 = lane + 32; v1 = p0; i1 = lane; }
    else         { v0 = p0; i0 = lane;      v1 = p1; i1 = lane + 32; }
    // warp merge to global top-2
    #pragma unroll
    for (int o = 16; o; o >>= 1) {
        float w0 = __shfl_xor_sync(~0u, v0, o); int j0 = __shfl_xor_sync(~0u, i0, o);
        float w1 = __shfl_xor_sync(~0u, v1, o); int j1 = __shfl_xor_sync(~0u, i1, o);
        if (w0 > v0 || (w0 == v0 && j0 < i0)) { v1 = v0; i1 = i0; v0 = w0; i0 = j0;
            if (w1 > v1 || (w1 == v1 && j1 < i1)) { v1 = w1; i1 = j1; } }
        else if (w0 > v1 || (w0 == v1 && j0 < i1)) { v1 = w0; i1 = j0; }
    }
    if (lane == 0) {
        float inv2 = 1.f / (v0 + v1 + 1e-9f);
        int p = t * 2;
        g_pe[p] = i0;     g_pw[p] = v0 * inv2;
        g_pe[p + 1] = i1; g_pw[p + 1] = v1 * inv2;
        atomicAdd(&g_cnt[i0], 1);
        atomicAdd(&g_cnt[i1], 1);
    }
}

__global__ void act_moe_kernel() {
    int idx = blockIdx.x * blockDim.x + threadIdx.x;
    if (idx < NPAIR * IMOE) {
        int r = idx >> 9, i = idx & 511;
        float g = g_h[r * 1024 + i];
        float u = g_h[r * 1024 + 512 + i];
        g_act[idx] = (g / (1.f + expf(-g))) * u;
    }
}

__global__ void act_sh_kernel() {
    int idx = blockIdx.x * blockDim.x + threadIdx.x;
    if (idx < TTOK * IMOE) {
        float g = g_hg[idx];
        g_acts[idx] = (g / (1.f + expf(-g))) * g_hu[idx];
    }
}

// ---------------- tiled SGEMM: C[m,n] = sum_k A[m,k] * B[n,k] ----------------
// MODE 0: dense, C[r*N+n] = v
// MODE 1: grouped (expert = blockIdx.z), A row via g_slot_tok, C = g_h at slot row
// MODE 2: grouped, A = g_act at slot row, atomicAdd into out[tok*N+n] scaled by slot_w
// MODE 3: dense, C[r*N+n] = g_shgate[r] * v
#define BM 64
#define BN 64
#define BKK 16

template <int MODE>
__global__ void __launch_bounds__(256)
gemm_kernel(const float* __restrict__ A, const float* __restrict__ B,
            float* __restrict__ C, int M, int N, int Kd, long bstride) {
    int e = blockIdx.z;
    int base = 0, mrows = M;
    if (MODE == 1 || MODE == 2) { base = g_off[e]; mrows = g_off[e + 1] - base; }
    int m0 = blockIdx.y * BM;
    if (m0 >= mrows) return;
    int n0 = blockIdx.x * BN;
    const float* Bp = B + (long)e * bstride;

    __shared__ float As[BKK][BM + 1];
    __shared__ __align__(16) float Bs[BKK][BN];

    int tid = threadIdx.x;
    int tx = tid & 15, ty = tid >> 4;
    int lr = tid >> 2;          // 0..63
    int lc = (tid & 3) * 4;     // 0,4,8,12

    bool avalid = (m0 + lr) < mrows;
    const float* Arow;
    if (MODE == 1) {
        int s_l = avalid ? (base + m0 + lr) : base;
        Arow = A + (long)g_slot_tok[s_l] * Kd;
    } else if (MODE == 2) {
        int s_l = avalid ? (base + m0 + lr) : base;
        Arow = A + (long)s_l * Kd;
    } else {
        Arow = A + (long)(avalid ? (m0 + lr) : 0) * Kd;
    }
    const float* Brow = Bp + (long)(n0 + lr) * Kd;

    float acc[4][4] = {};
    for (int k0 = 0; k0 < Kd; k0 += BKK) {
        float4 av = avalid ? *(const float4*)(Arow + k0 + lc) : make_float4(0.f, 0.f, 0.f, 0.f);
        float4 bv = *(const float4*)(Brow + k0 + lc);
        As[lc + 0][lr] = av.x; As[lc + 1][lr] = av.y;
        As[lc + 2][lr] = av.z; As[lc + 3][lr] = av.w;
        Bs[lc + 0][lr] = bv.x; Bs[lc + 1][lr] = bv.y;
        Bs[lc + 2][lr] = bv.z; Bs[lc + 3][lr] = bv.w;
        __syncthreads();
        #pragma unroll
        for (int kk = 0; kk < BKK; kk++) {
            float a[4];
            #pragma unroll
            for (int i = 0; i < 4; i++) a[i] = As[kk][ty * 4 + i];
            float4 b4 = *(const float4*)(&Bs[kk][tx * 4]);
            float b[4] = {b4.x, b4.y, b4.z, b4.w};
            #pragma unroll
            for (int i = 0; i < 4; i++)
                #pragma unroll
                for (int j = 0; j < 4; j++) acc[i][j] += a[i] * b[j];
        }
        __syncthreads();
    }

    #pragma unroll
    for (int i = 0; i < 4; i++) {
        int r = m0 + ty * 4 + i;
        if (r >= mrows) break;
        int s = base + r;
        #pragma unroll
        for (int j = 0; j < 4; j++) {
            int n = n0 + tx * 4 + j;
            float v = acc[i][j];
            if (MODE == 0)      C[(long)r * N + n] = v;
            else if (MODE == 1) C[(long)s * N + n] = v;
            else if (MODE == 2) atomicAdd(&C[(long)g_slot_tok[s] * N + n], g_slot_w[s] * v);
            else                C[(long)r * N + n] = g_shgate[r] * v;
        }
    }
}

// ---------------- launch ----------------
extern "C" void kernel_launch(void* const* d_in, const int* in_sizes, int n_in,
                              void* d_out, int out_size) {
    const float* x       = (const float*)d_in[0];  // [4096,1024]
    const float* rw      = (const float*)d_in[1];  // [64,1024]
    const float* gate_up = (const float*)d_in[2];  // [64,1024,1024]
    const float* down    = (const float*)d_in[3];  // [64,1024,512]
    const float* shg     = (const float*)d_in[4];  // [512,1024]
    const float* shu     = (const float*)d_in[5];  // [512,1024]
    const float* shd     = (const float*)d_in[6];  // [1024,512]
    const float* sheg    = (const float*)d_in[7];  // [1,1024]

    float* out = (float*)d_out;
    float* probs = nullptr;
    if (out_size >= (int)(TTOK * DHID + TTOK * NEXP))
        probs = out + (size_t)TTOK * DHID;

    float *p_h, *p_act, *p_hg, *p_hu, *p_acts, *p_logits;
    cudaGetSymbolAddress((void**)&p_h, g_h);
    cudaGetSymbolAddress((void**)&p_act, g_act);
    cudaGetSymbolAddress((void**)&p_hg, g_hg);
    cudaGetSymbolAddress((void**)&p_hu, g_hu);
    cudaGetSymbolAddress((void**)&p_acts, g_acts);
    cudaGetSymbolAddress((void**)&p_logits, g_logits);

    // 1) router logits = x @ rw^T  [4096, 64]
    gemm_kernel<0><<<dim3(1, TTOK / BM, 1), 256>>>(x, rw, p_logits, TTOK, NEXP, DHID, 0);
    // 2) reset counts, softmax+top2+gate
    zero_kernel<<<1, 64>>>();
    softmax_topk_kernel<<<TTOK / 8, 256>>>(x, sheg, probs);
    // 3) group pairs by expert
    scan_kernel<<<1, 32>>>();
    scatter_kernel<<<NPAIR / 256, 256>>>();
    // 4) routed gate_up:  g_h[slot, 0:1024] = x[tok] @ gate_up[e]^T
    gemm_kernel<1><<<dim3(2 * IMOE / BN, 8, NEXP), 256>>>(
        x, gate_up, p_h, 0, 2 * IMOE, DHID, (long)2 * IMOE * DHID);
    // 5) routed swiglu activation
    act_moe_kernel<<<NPAIR * IMOE / 256, 256>>>();
    // 6) shared expert gate/up GEMMs
    gemm_kernel<0><<<dim3(IMOE / BN, TTOK / BM, 1), 256>>>(x, shg, p_hg, TTOK, IMOE, DHID, 0);
    gemm_kernel<0><<<dim3(IMOE / BN, TTOK / BM, 1), 256>>>(x, shu, p_hu, TTOK, IMOE, DHID, 0);
    act_sh_kernel<<<TTOK * IMOE / 256, 256>>>();
    // 7) shared down + sigmoid-gate epilogue -> writes full out (no pre-zero needed)
    gemm_kernel<3><<<dim3(DHID / BN, TTOK / BM, 1), 256>>>(p_acts, shd, out, TTOK, DHID, IMOE, 0);
    // 8) routed down + weighted atomic scatter-add into out
    gemm_kernel<2><<<dim3(DHID / BN, 8, NEXP), 256>>>(
        p_act, down, out, 0, DHID, IMOE, (long)DHID * IMOE);
}

// round 5
// speedup vs baseline: 1.6164x; 1.6164x over previous
#include <cuda_runtime.h>
#include <math.h>
#include <stdint.h>

#define TTOK 4096
#define DHID 1024
#define NEXP 64
#define IMOE 512
#define NPAIR 8192

// ---------------- scratch (static device globals) ----------------
__device__ int   g_cnt[NEXP];
__device__ int   g_off[NEXP + 1];
__device__ int   g_fill[NEXP];
__device__ int   g_pe[NPAIR];
__device__ float g_pw[NPAIR];
__device__ int   g_slot_tok[NPAIR];
__device__ float g_slot_w[NPAIR];
__device__ float g_shgate[TTOK];
__device__ float g_logits[TTOK * NEXP];
__device__ float g_act[NPAIR * IMOE];      // routed activated  [8192,512]
__device__ float g_acts[TTOK * IMOE];      // shared activated  [4096,512]

// ---------------- helpers ----------------
__device__ __forceinline__ uint32_t smem_u32(const void* p) {
    uint32_t a;
    asm("{ .reg .u64 t; cvta.to.shared.u64 t, %1; cvt.u32.u64 %0, t; }" : "=r"(a) : "l"(p));
    return a;
}
__device__ __forceinline__ void cpa16(uint32_t d, const float* s) {
    asm volatile("cp.async.cg.shared.global [%0], [%1], 16;" :: "r"(d), "l"(s) : "memory");
}
__device__ __forceinline__ void cpcommit() {
    asm volatile("cp.async.commit_group;" ::: "memory");
}
__device__ __forceinline__ void cpwait1() {
    asm volatile("cp.async.wait_group 1;" ::: "memory");
}
__device__ __forceinline__ void cpwait0() {
    asm volatile("cp.async.wait_group 0;" ::: "memory");
}
// D += A(row m16k8, tf32) * B(col k8n8, tf32), fp32 acc
__device__ __forceinline__ void mma8(float* c, const uint32_t* a, uint32_t b0, uint32_t b1) {
    asm volatile(
        "mma.sync.aligned.m16n8k8.row.col.f32.tf32.tf32.f32 "
        "{%0,%1,%2,%3}, {%4,%5,%6,%7}, {%8,%9}, {%0,%1,%2,%3};"
        : "+f"(c[0]), "+f"(c[1]), "+f"(c[2]), "+f"(c[3])
        : "r"(a[0]), "r"(a[1]), "r"(a[2]), "r"(a[3]), "r"(b0), "r"(b1));
}
// 3xTF32 split: v = hi + lo with hi, lo tf32-representable
__device__ __forceinline__ void tfsplit(float v, uint32_t& hi, uint32_t& lo) {
    uint32_t h;
    asm("cvt.rna.tf32.f32 %0, %1;" : "=r"(h) : "f"(v));
    float r = v - __uint_as_float(h);
    uint32_t l;
    asm("cvt.rna.tf32.f32 %0, %1;" : "=r"(l) : "f"(r));
    hi = h; lo = l;
}
__device__ __forceinline__ int imin(int a, int b) { return a < b ? a : b; }

// ---------------- tiny kernels ----------------
__global__ void zero_kernel() {
    if (threadIdx.x < NEXP) g_cnt[threadIdx.x] = 0;
}
__global__ void scan_kernel() {
    if (threadIdx.x == 0) {
        int a = 0;
        for (int e = 0; e < NEXP; e++) { g_off[e] = a; g_fill[e] = a; a += g_cnt[e]; }
        g_off[NEXP] = a;
    }
}
__global__ void scatter_kernel() {
    int p = blockIdx.x * blockDim.x + threadIdx.x;
    if (p < NPAIR) {
        int e = g_pe[p];
        int s = atomicAdd(&g_fill[e], 1);
        g_slot_tok[s] = p >> 1;
        g_slot_w[s]   = g_pw[p];
    }
}

__global__ void softmax_topk_kernel(const float* __restrict__ x,
                                    const float* __restrict__ sheg,
                                    float* __restrict__ probs_out) {
    int w = threadIdx.x >> 5, lane = threadIdx.x & 31;
    int t = blockIdx.x * 8 + w;
    if (t >= TTOK) return;

    const float* xr = x + (size_t)t * DHID;
    float sd = 0.f;
    for (int k = lane; k < DHID; k += 32) sd += xr[k] * sheg[k];
    #pragma unroll
    for (int o = 16; o; o >>= 1) sd += __shfl_xor_sync(~0u, sd, o);
    if (lane == 0) g_shgate[t] = 1.f / (1.f + expf(-sd));

    float l0 = g_logits[t * 64 + lane];
    float l1 = g_logits[t * 64 + 32 + lane];
    float m = fmaxf(l0, l1);
    #pragma unroll
    for (int o = 16; o; o >>= 1) m = fmaxf(m, __shfl_xor_sync(~0u, m, o));
    float e0 = expf(l0 - m), e1 = expf(l1 - m);
    float s = e0 + e1;
    #pragma unroll
    for (int o = 16; o; o >>= 1) s += __shfl_xor_sync(~0u, s, o);
    float inv = 1.f / s;
    float p0 = e0 * inv, p1 = e1 * inv;
    if (probs_out) {
        probs_out[t * 64 + lane]      = p0;
        probs_out[t * 64 + 32 + lane] = p1;
    }
    float v0, v1; int i0, i1;
    if (p1 > p0) { v0 = p1; i0 = lane + 32; v1 = p0; i1 = lane; }
    else         { v0 = p0; i0 = lane;      v1 = p1; i1 = lane + 32; }
    #pragma unroll
    for (int o = 16; o; o >>= 1) {
        float w0 = __shfl_xor_sync(~0u, v0, o); int j0 = __shfl_xor_sync(~0u, i0, o);
        float w1 = __shfl_xor_sync(~0u, v1, o); int j1 = __shfl_xor_sync(~0u, i1, o);
        if (w0 > v0 || (w0 == v0 && j0 < i0)) { v1 = v0; i1 = i0; v0 = w0; i0 = j0;
            if (w1 > v1 || (w1 == v1 && j1 < i1)) { v1 = w1; i1 = j1; } }
        else if (w0 > v1 || (w0 == v1 && j0 < i1)) { v1 = w0; i1 = j0; }
    }
    if (lane == 0) {
        float inv2 = 1.f / (v0 + v1 + 1e-9f);
        int p = t * 2;
        g_pe[p] = i0;     g_pw[p] = v0 * inv2;
        g_pe[p + 1] = i1; g_pw[p + 1] = v1 * inv2;
        atomicAdd(&g_cnt[i0], 1);
        atomicAdd(&g_cnt[i1], 1);
    }
}

// ---------------- fp32 SIMT GEMM for router logits (precision-critical) ----------------
__global__ void __launch_bounds__(256)
logits_gemm(const float* __restrict__ A, const float* __restrict__ B,
            float* __restrict__ C) {
    const int N = 64, Kd = 1024;
    __shared__ float As[16][65];
    __shared__ __align__(16) float Bs[16][64];
    int tid = threadIdx.x;
    int m0 = blockIdx.y * 64;
    int tx = tid & 15, ty = tid >> 4;
    int lr = tid >> 2, lc = (tid & 3) * 4;
    const float* Arow = A + (long)(m0 + lr) * Kd;
    const float* Brow = B + (long)lr * Kd;
    float acc[4][4] = {};
    for (int k0 = 0; k0 < Kd; k0 += 16) {
        float4 av = *(const float4*)(Arow + k0 + lc);
        float4 bv = *(const float4*)(Brow + k0 + lc);
        As[lc + 0][lr] = av.x; As[lc + 1][lr] = av.y;
        As[lc + 2][lr] = av.z; As[lc + 3][lr] = av.w;
        Bs[lc + 0][lr] = bv.x; Bs[lc + 1][lr] = bv.y;
        Bs[lc + 2][lr] = bv.z; Bs[lc + 3][lr] = bv.w;
        __syncthreads();
        #pragma unroll
        for (int kk = 0; kk < 16; kk++) {
            float a[4];
            #pragma unroll
            for (int i = 0; i < 4; i++) a[i] = As[kk][ty * 4 + i];
            float4 b4 = *(const float4*)(&Bs[kk][tx * 4]);
            float b[4] = {b4.x, b4.y, b4.z, b4.w};
            #pragma unroll
            for (int i = 0; i < 4; i++)
                #pragma unroll
                for (int j = 0; j < 4; j++) acc[i][j] += a[i] * b[j];
        }
        __syncthreads();
    }
    #pragma unroll
    for (int i = 0; i < 4; i++)
        #pragma unroll
        for (int j = 0; j < 4; j++)
            C[(long)(m0 + ty * 4 + i) * N + tx * 4 + j] = acc[i][j];
}

// ------- 3xTF32 mma.sync GEMM, CTA 128x128, warp 32x64, BK=16 -------
// C[m,n] = sum_k A[m,k]*B[n,k], fp32-equivalent accuracy via hi/lo tf32 split.
// MODE 0: shared gate/up fused (B rows interleaved even=shg, odd=shu);
//         epilogue g_acts[m, jx*64+c] = silu(g)*u
// MODE 1: routed gate/up fused (expert=blockIdx.z, A via g_slot_tok) -> g_act
// MODE 2: routed down (A=g_act slots, K=512); atomicAdd out[tok,n] += w*v
// MODE 3: shared down (A=g_acts, K=512); out[m,n] = shgate[m]*v
template <int MODE>
__global__ void __launch_bounds__(256)
mma_gemm(const float* __restrict__ A, const float* __restrict__ B1,
         const float* __restrict__ B2, float* __restrict__ C) {
    constexpr int Kd  = (MODE == 2 || MODE == 3) ? 512 : 1024;
    constexpr int NIT = Kd / 16;

    __shared__ float As[2][128][20];
    __shared__ float Bs[2][128][20];

    int tid = threadIdx.x, lane = tid & 31, wid = tid >> 5;
    int e = blockIdx.z;
    int m0 = blockIdx.y * 128;
    int jx = blockIdx.x;
    int base = 0, cnt = 1 << 30;
    if (MODE == 1 || MODE == 2) {
        base = g_off[e];
        cnt = g_off[e + 1] - base;
        if (m0 >= cnt) return;
    }

    // ---- loader setup: thread t loads rows (t>>2), (t>>2)+64; k cols (t&3)*4..+3
    int lr = tid >> 2, lc4 = (tid & 3) * 4;
    const float* aptr[2];
    const float* bptr[2];
    #pragma unroll
    for (int h = 0; h < 2; h++) {
        int r = lr + h * 64;
        long ai;
        if (MODE == 1)      { int s = base + imin(m0 + r, cnt - 1); ai = (long)g_slot_tok[s] * 1024; }
        else if (MODE == 2) { int s = base + imin(m0 + r, cnt - 1); ai = (long)s * 512; }
        else                  ai = (long)(m0 + r) * Kd;
        aptr[h] = A + ai + lc4;

        int br = r;
        const float* p;
        if (MODE == 0) {
            int col = jx * 64 + (br >> 1);
            p = ((br & 1) ? B2 : B1) + (long)col * 1024;
        } else if (MODE == 1) {
            int col = jx * 64 + (br >> 1);
            int row = (br & 1) ? (512 + col) : col;
            p = B1 + ((long)e << 20) + (long)row * 1024;
        } else if (MODE == 2) {
            p = B1 + (long)e * (1024 * 512) + (long)(jx * 128 + br) * 512;
        } else {
            p = B1 + (long)(jx * 128 + br) * 512;
        }
        bptr[h] = p + lc4;
    }
    uint32_t uA = smem_u32(&As[0][0][0]);
    uint32_t uB = smem_u32(&Bs[0][0][0]);
    uint32_t dA[2][2], dB[2][2];
    #pragma unroll
    for (int p = 0; p < 2; p++)
        #pragma unroll
        for (int h = 0; h < 2; h++) {
            dA[p][h] = uA + (uint32_t)(((p * 128 + lr + h * 64) * 20 + lc4) * 4);
            dB[p][h] = uB + (uint32_t)(((p * 128 + lr + h * 64) * 20 + lc4) * 4);
        }

    // ---- compute setup
    int g = lane >> 2, tg = lane & 3;
    int wm = wid >> 1, wn = wid & 1;
    int m0w = wm * 32, n0w = wn * 64;
    float acc[2][8][4] = {};

    #pragma unroll
    for (int h = 0; h < 2; h++) { cpa16(dA[0][h], aptr[h]); cpa16(dB[0][h], bptr[h]); }
    cpcommit();

    for (int it = 0; it < NIT; it++) {
        if (it + 1 < NIT) {
            int pn = (it + 1) & 1, k0 = (it + 1) * 16;
            #pragma unroll
            for (int h = 0; h < 2; h++) {
                cpa16(dA[pn][h], aptr[h] + k0);
                cpa16(dB[pn][h], bptr[h] + k0);
            }
            cpcommit();
            cpwait1();
        } else {
            cpwait0();
        }
        __syncthreads();
        int p = it & 1;
        #pragma unroll
        for (int ks = 0; ks < 2; ks++) {
            int kc = ks * 8 + tg;
            uint32_t ah[2][4], al[2][4];
            #pragma unroll
            for (int mt = 0; mt < 2; mt++) {
                int rr = m0w + mt * 16 + g;
                tfsplit(As[p][rr][kc],          ah[mt][0], al[mt][0]);
                tfsplit(As[p][rr + 8][kc],      ah[mt][1], al[mt][1]);
                tfsplit(As[p][rr][kc + 4],      ah[mt][2], al[mt][2]);
                tfsplit(As[p][rr + 8][kc + 4],  ah[mt][3], al[mt][3]);
            }
            #pragma unroll
            for (int nt = 0; nt < 8; nt++) {
                int nr = n0w + nt * 8 + g;
                uint32_t b0h, b0l, b1h, b1l;
                tfsplit(Bs[p][nr][kc],     b0h, b0l);
                tfsplit(Bs[p][nr][kc + 4], b1h, b1l);
                #pragma unroll
                for (int mt = 0; mt < 2; mt++) {
                    mma8(acc[mt][nt], al[mt], b0h, b1h);  // a_lo * b_hi
                    mma8(acc[mt][nt], ah[mt], b0l, b1l);  // a_hi * b_lo
                    mma8(acc[mt][nt], ah[mt], b0h, b1h);  // a_hi * b_hi
                }
            }
        }
        __syncthreads();
    }

    // ---- epilogue
    if (MODE == 0 || MODE == 1) {
        #pragma unroll
        for (int mt = 0; mt < 2; mt++) {
            #pragma unroll
            for (int half = 0; half < 2; half++) {
                int mr = m0 + m0w + mt * 16 + g + half * 8;
                bool v = (MODE == 0) ? true : (mr < cnt);
                if (v) {
                    long orow = (MODE == 0) ? (long)mr : (long)(base + mr);
                    float* o = C + orow * 512 + jx * 64 + (n0w >> 1) + tg;
                    #pragma unroll
                    for (int nt = 0; nt < 8; nt++) {
                        float gg = acc[mt][nt][half * 2];
                        float uu = acc[mt][nt][half * 2 + 1];
                        o[nt * 4] = (gg / (1.f + expf(-gg))) * uu;
                    }
                }
            }
        }
    } else if (MODE == 2) {
        #pragma unroll
        for (int mt = 0; mt < 2; mt++) {
            #pragma unroll
            for (int half = 0; half < 2; half++) {
                int mr = m0 + m0w + mt * 16 + g + half * 8;
                if (mr < cnt) {
                    int s = base + mr;
                    int tok = g_slot_tok[s];
                    float wv = g_slot_w[s];
                    float* o = C + (long)tok * 1024 + jx * 128 + n0w + 2 * tg;
                    #pragma unroll
                    for (int nt = 0; nt < 8; nt++) {
                        atomicAdd(&o[nt * 8],     wv * acc[mt][nt][half * 2]);
                        atomicAdd(&o[nt * 8 + 1], wv * acc[mt][nt][half * 2 + 1]);
                    }
                }
            }
        }
    } else {
        #pragma unroll
        for (int mt = 0; mt < 2; mt++) {
            #pragma unroll
            for (int half = 0; half < 2; half++) {
                int mr = m0 + m0w + mt * 16 + g + half * 8;
                float sg = g_shgate[mr];
                float* o = C + (long)mr * 1024 + jx * 128 + n0w + 2 * tg;
                #pragma unroll
                for (int nt = 0; nt < 8; nt++) {
                    o[nt * 8]     = sg * acc[mt][nt][half * 2];
                    o[nt * 8 + 1] = sg * acc[mt][nt][half * 2 + 1];
                }
            }
        }
    }
}

// ---------------- launch ----------------
extern "C" void kernel_launch(void* const* d_in, const int* in_sizes, int n_in,
                              void* d_out, int out_size) {
    const float* x       = (const float*)d_in[0];  // [4096,1024]
    const float* rw      = (const float*)d_in[1];  // [64,1024]
    const float* gate_up = (const float*)d_in[2];  // [64,1024,1024]
    const float* down    = (const float*)d_in[3];  // [64,1024,512]
    const float* shg     = (const float*)d_in[4];  // [512,1024]
    const float* shu     = (const float*)d_in[5];  // [512,1024]
    const float* shd     = (const float*)d_in[6];  // [1024,512]
    const float* sheg    = (const float*)d_in[7];  // [1,1024]

    float* out = (float*)d_out;
    float* probs = nullptr;
    if (out_size >= (int)(TTOK * DHID + TTOK * NEXP))
        probs = out + (size_t)TTOK * DHID;

    float *p_act, *p_acts, *p_logits;
    cudaGetSymbolAddress((void**)&p_act, g_act);
    cudaGetSymbolAddress((void**)&p_acts, g_acts);
    cudaGetSymbolAddress((void**)&p_logits, g_logits);

    // 1) router logits (fp32 SIMT — top-k selection is precision-critical)
    logits_gemm<<<dim3(1, TTOK / 64), 256>>>(x, rw, p_logits);
    // 2) softmax + top2 + shared-expert gate
    zero_kernel<<<1, 64>>>();
    softmax_topk_kernel<<<TTOK / 8, 256>>>(x, sheg, probs);
    // 3) group (token, slot) pairs by expert
    scan_kernel<<<1, 32>>>();
    scatter_kernel<<<NPAIR / 256, 256>>>();
    // 4) routed gate_up + fused swiglu -> g_act
    mma_gemm<1><<<dim3(8, 2, NEXP), 256>>>(x, gate_up, nullptr, p_act);
    // 5) shared gate/up + fused swiglu -> g_acts
    mma_gemm<0><<<dim3(8, TTOK / 128), 256>>>(x, shg, shu, p_acts);
    // 6) shared down + sigmoid-gate -> out (full overwrite, before atomics)
    mma_gemm<3><<<dim3(8, TTOK / 128), 256>>>(p_acts, shd, nullptr, out);
    // 7) routed down + weighted atomic scatter-add -> out
    mma_gemm<2><<<dim3(8, 2, NEXP), 256>>>(p_act, down, nullptr, out);
}

// round 7
// speedup vs baseline: 2.6936x; 1.6664x over previous
#include <cuda_runtime.h>
#include <cuda_fp16.h>
#include <math.h>
#include <stdint.h>

#define TTOK 4096
#define DHID 1024
#define NEXP 64
#define IMOE 512
#define NPAIR 8192

// ---------------- scratch (static device globals) ----------------
__device__ int   g_cnt[NEXP];
__device__ int   g_off[NEXP + 1];
__device__ int   g_fill[NEXP];
__device__ int   g_pe[NPAIR];
__device__ float g_pw[NPAIR];
__device__ int   g_slot_tok[NPAIR];
__device__ int   g_pair_slot[NPAIR];
__device__ float g_shgate[TTOK];
__device__ float g_logits[TTOK * NEXP];
__device__ float g_act[NPAIR * IMOE];        // routed activated   [8192,512]
__device__ float g_acts[TTOK * IMOE];        // shared activated   [4096,512]
__device__ float g_y[NPAIR * DHID];          // routed down output [8192,1024]

// ---------------- helpers ----------------
__device__ __forceinline__ uint32_t smem_u32(const void* p) {
    uint32_t a;
    asm("{ .reg .u64 t; cvta.to.shared.u64 t, %1; cvt.u32.u64 %0, t; }" : "=r"(a) : "l"(p));
    return a;
}
__device__ __forceinline__ void ldsm4(uint32_t& d0, uint32_t& d1, uint32_t& d2, uint32_t& d3,
                                      uint32_t a) {
    asm volatile("ldmatrix.sync.aligned.m8n8.x4.shared.b16 {%0,%1,%2,%3}, [%4];"
                 : "=r"(d0), "=r"(d1), "=r"(d2), "=r"(d3) : "r"(a));
}
// D += A(m16k16 f16) * B(k16n8 f16), fp32 acc
__device__ __forceinline__ void mma16(float* c, const uint32_t* a, uint32_t b0, uint32_t b1) {
    asm volatile(
        "mma.sync.aligned.m16n8k16.row.col.f32.f16.f16.f32 "
        "{%0,%1,%2,%3}, {%4,%5,%6,%7}, {%8,%9}, {%0,%1,%2,%3};"
        : "+f"(c[0]), "+f"(c[1]), "+f"(c[2]), "+f"(c[3])
        : "r"(a[0]), "r"(a[1]), "r"(a[2]), "r"(a[3]), "r"(b0), "r"(b1));
}
__device__ __forceinline__ uint32_t h2u(__half2 h) {
    uint32_t u;
    memcpy(&u, &h, 4);
    return u;
}
// fp16 hi/lo split of 4 floats -> packed f16x2 pairs
__device__ __forceinline__ void split4(float4 v, uint2& hi, uint2& lo) {
    __half2 h01 = __floats2half2_rn(v.x, v.y);
    __half2 h23 = __floats2half2_rn(v.z, v.w);
    float2 f01 = __half22float2(h01);
    float2 f23 = __half22float2(h23);
    __half2 l01 = __floats2half2_rn(v.x - f01.x, v.y - f01.y);
    __half2 l23 = __floats2half2_rn(v.z - f23.x, v.w - f23.y);
    hi = make_uint2(h2u(h01), h2u(h23));
    lo = make_uint2(h2u(l01), h2u(l23));
}
__device__ __forceinline__ int imin(int a, int b) { return a < b ? a : b; }

// ---------------- tiny kernels ----------------
__global__ void zero_kernel() {
    if (threadIdx.x < NEXP) g_cnt[threadIdx.x] = 0;
}
__global__ void scan_kernel() {
    if (threadIdx.x == 0) {
        int a = 0;
        for (int e = 0; e < NEXP; e++) { g_off[e] = a; g_fill[e] = a; a += g_cnt[e]; }
        g_off[NEXP] = a;
    }
}
__global__ void scatter_kernel() {
    int p = blockIdx.x * blockDim.x + threadIdx.x;
    if (p < NPAIR) {
        int e = g_pe[p];
        int s = atomicAdd(&g_fill[e], 1);
        g_slot_tok[s] = p >> 1;
        g_pair_slot[p] = s;
    }
}

__global__ void softmax_topk_kernel(const float* __restrict__ x,
                                    const float* __restrict__ sheg,
                                    float* __restrict__ probs_out) {
    int w = threadIdx.x >> 5, lane = threadIdx.x & 31;
    int t = blockIdx.x * 8 + w;
    if (t >= TTOK) return;

    const float* xr = x + (size_t)t * DHID;
    float sd = 0.f;
    for (int k = lane; k < DHID; k += 32) sd += xr[k] * sheg[k];
    #pragma unroll
    for (int o = 16; o; o >>= 1) sd += __shfl_xor_sync(~0u, sd, o);
    if (lane == 0) g_shgate[t] = 1.f / (1.f + expf(-sd));

    float l0 = g_logits[t * 64 + lane];
    float l1 = g_logits[t * 64 + 32 + lane];
    float m = fmaxf(l0, l1);
    #pragma unroll
    for (int o = 16; o; o >>= 1) m = fmaxf(m, __shfl_xor_sync(~0u, m, o));
    float e0 = expf(l0 - m), e1 = expf(l1 - m);
    float s = e0 + e1;
    #pragma unroll
    for (int o = 16; o; o >>= 1) s += __shfl_xor_sync(~0u, s, o);
    float inv = 1.f / s;
    float p0 = e0 * inv, p1 = e1 * inv;
    if (probs_out) {
        probs_out[t * 64 + lane]      = p0;
        probs_out[t * 64 + 32 + lane] = p1;
    }
    float v0, v1; int i0, i1;
    if (p1 > p0) { v0 = p1; i0 = lane + 32; v1 = p0; i1 = lane; }
    else         { v0 = p0; i0 = lane;      v1 = p1; i1 = lane + 32; }
    #pragma unroll
    for (int o = 16; o; o >>= 1) {
        float w0 = __shfl_xor_sync(~0u, v0, o); int j0 = __shfl_xor_sync(~0u, i0, o);
        float w1 = __shfl_xor_sync(~0u, v1, o); int j1 = __shfl_xor_sync(~0u, i1, o);
        if (w0 > v0 || (w0 == v0 && j0 < i0)) { v1 = v0; i1 = i0; v0 = w0; i0 = j0;
            if (w1 > v1 || (w1 == v1 && j1 < i1)) { v1 = w1; i1 = j1; } }
        else if (w0 > v1 || (w0 == v1 && j0 < i1)) { v1 = w0; i1 = j0; }
    }
    if (lane == 0) {
        float inv2 = 1.f / (v0 + v1 + 1e-9f);
        int p = t * 2;
        g_pe[p] = i0;     g_pw[p] = v0 * inv2;
        g_pe[p + 1] = i1; g_pw[p + 1] = v1 * inv2;
        atomicAdd(&g_cnt[i0], 1);
        atomicAdd(&g_cnt[i1], 1);
    }
}

// final combine: out[t] += w0*y[slot0] + w1*y[slot1]   (out already holds shared part)
__global__ void combine_kernel(float* __restrict__ out) {
    int w = threadIdx.x >> 5, lane = threadIdx.x & 31;
    int t = blockIdx.x * 8 + w;
    if (t >= TTOK) return;
    int s0 = g_pair_slot[2 * t], s1 = g_pair_slot[2 * t + 1];
    float w0 = g_pw[2 * t], w1 = g_pw[2 * t + 1];
    float4* o = (float4*)(out + (long)t * DHID);
    const float4* y0 = (const float4*)(g_y + (long)s0 * DHID);
    const float4* y1 = (const float4*)(g_y + (long)s1 * DHID);
    for (int i = lane; i < DHID / 4; i += 32) {
        float4 a = o[i], b = y0[i], c = y1[i];
        a.x += w0 * b.x + w1 * c.x;
        a.y += w0 * b.y + w1 * c.y;
        a.z += w0 * b.z + w1 * c.z;
        a.w += w0 * b.w + w1 * c.w;
        o[i] = a;
    }
}

// ---------------- fp32 SIMT GEMM for router logits (precision-critical) ----------------
__global__ void __launch_bounds__(256)
logits_gemm(const float* __restrict__ A, const float* __restrict__ B,
            float* __restrict__ C) {
    const int N = 64, Kd = 1024;
    __shared__ float As[16][65];
    __shared__ __align__(16) float Bs[16][64];
    int tid = threadIdx.x;
    int m0 = blockIdx.y * 64;
    int tx = tid & 15, ty = tid >> 4;
    int lr = tid >> 2, lc = (tid & 3) * 4;
    const float* Arow = A + (long)(m0 + lr) * Kd;
    const float* Brow = B + (long)lr * Kd;
    float acc[4][4] = {};
    for (int k0 = 0; k0 < Kd; k0 += 16) {
        float4 av = *(const float4*)(Arow + k0 + lc);
        float4 bv = *(const float4*)(Brow + k0 + lc);
        As[lc + 0][lr] = av.x; As[lc + 1][lr] = av.y;
        As[lc + 2][lr] = av.z; As[lc + 3][lr] = av.w;
        Bs[lc + 0][lr] = bv.x; Bs[lc + 1][lr] = bv.y;
        Bs[lc + 2][lr] = bv.z; Bs[lc + 3][lr] = bv.w;
        __syncthreads();
        #pragma unroll
        for (int kk = 0; kk < 16; kk++) {
            float a[4];
            #pragma unroll
            for (int i = 0; i < 4; i++) a[i] = As[kk][ty * 4 + i];
            float4 b4 = *(const float4*)(&Bs[kk][tx * 4]);
            float b[4] = {b4.x, b4.y, b4.z, b4.w};
            #pragma unroll
            for (int i = 0; i < 4; i++)
                #pragma unroll
                for (int j = 0; j < 4; j++) acc[i][j] += a[i] * b[j];
        }
        __syncthreads();
    }
    #pragma unroll
    for (int i = 0; i < 4; i++)
        #pragma unroll
        for (int j = 0; j < 4; j++)
            C[(long)(m0 + ty * 4 + i) * N + tx * 4 + j] = acc[i][j];
}

// ------- 3xFP16 mma.sync GEMM, CTA 128x128, warp 32x64, BK=16 -------
// Loader splits fp32 -> (hi, lo) fp16 tiles in smem ONCE; compute uses ldmatrix.
// C = A*B^T with fp32-equivalent accuracy (a_hi*b_hi + a_hi*b_lo + a_lo*b_hi).
// MODE 0: shared gate/up fused (B rows interleaved even=shg, odd=shu) -> g_acts
// MODE 1: routed gate/up fused (expert=blockIdx.z, A via g_slot_tok) -> g_act
// MODE 2: routed down (A=g_act slots, K=512); plain store to g_y[slot]
// MODE 3: shared down (A=g_acts, K=512); out[m,n] = shgate[m]*v
#define RS 24   // smem row stride in halves (48B): conflict-free for ldmatrix
#define TILEH (128 * RS)  // halves per tile buffer

template <int MODE>
__global__ void __launch_bounds__(256, 2)
mma_gemm(const float* __restrict__ A, const float* __restrict__ B1,
         const float* __restrict__ B2, float* __restrict__ C) {
    constexpr int Kd  = (MODE == 2 || MODE == 3) ? 512 : 1024;
    constexpr int NIT = Kd / 16;

    extern __shared__ __align__(16) __half dynsm[];
    __half* pAh = dynsm;                 // [2][128][RS]
    __half* pAl = dynsm + 2 * TILEH;
    __half* pBh = dynsm + 4 * TILEH;
    __half* pBl = dynsm + 6 * TILEH;

    int tid = threadIdx.x, lane = tid & 31, wid = tid >> 5;
    int e = blockIdx.z;
    int m0 = blockIdx.y * 128;
    int jx = blockIdx.x;
    int base = 0, cnt = 1 << 30;
    if (MODE == 1 || MODE == 2) {
        base = g_off[e];
        cnt = g_off[e + 1] - base;
        if (m0 >= cnt) return;
    }

    // ---- loader: thread handles rows r0, r0+64; k quad q
    int r0 = tid >> 2, q = (tid & 3) * 4;
    const float* aptr[2];
    const float* bptr[2];
    #pragma unroll
    for (int h = 0; h < 2; h++) {
        int r = r0 + h * 64;
        long ai;
        if (MODE == 1)      { int s = base + imin(m0 + r, cnt - 1); ai = (long)g_slot_tok[s] * 1024; }
        else if (MODE == 2) { int s = base + imin(m0 + r, cnt - 1); ai = (long)s * 512; }
        else                  ai = (long)(m0 + r) * Kd;
        aptr[h] = A + ai + q;

        const float* p;
        if (MODE == 0) {
            int col = jx * 64 + (r >> 1);
            p = ((r & 1) ? B2 : B1) + (long)col * 1024;
        } else if (MODE == 1) {
            int col = jx * 64 + (r >> 1);
            int row = (r & 1) ? (512 + col) : col;
            p = B1 + ((long)e << 20) + (long)row * 1024;
        } else if (MODE == 2) {
            p = B1 + (long)e * (1024 * 512) + (long)(jx * 128 + r) * 512;
        } else {
            p = B1 + (long)(jx * 128 + r) * 512;
        }
        bptr[h] = p + q;
    }

    // ---- ldmatrix lane offsets (bytes within a tile buffer)
    int wm = wid >> 1, wn = wid & 1;
    int m0w = wm * 32, n0w = wn * 64;
    uint32_t offA[2], offB[4];
    #pragma unroll
    for (int mt = 0; mt < 2; mt++) {
        int row = m0w + mt * 16 + ((lane >> 3) & 1) * 8 + (lane & 7);
        int col = ((lane >> 4) & 1) * 8;
        offA[mt] = (uint32_t)((row * RS + col) * 2);
    }
    #pragma unroll
    for (int nb = 0; nb < 4; nb++) {
        int row = n0w + nb * 16 + ((lane >> 4) & 1) * 8 + (lane & 7);
        int col = ((lane >> 3) & 1) * 8;
        offB[nb] = (uint32_t)((row * RS + col) * 2);
    }
    uint32_t uAh = smem_u32(pAh), uAl = smem_u32(pAl);
    uint32_t uBh = smem_u32(pBh), uBl = smem_u32(pBl);

    float acc[2][8][4] = {};

    // prologue: stage tile 0
    float4 sa[2], sb[2];
    #pragma unroll
    for (int h = 0; h < 2; h++) { sa[h] = *(const float4*)aptr[h]; sb[h] = *(const float4*)bptr[h]; }

    for (int it = 0; it < NIT; it++) {
        int p = it & 1;
        // split + STS current staged tile
        #pragma unroll
        for (int h = 0; h < 2; h++) {
            int r = r0 + h * 64;
            uint2 hi, lo;
            split4(sa[h], hi, lo);
            *(uint2*)&pAh[p * TILEH + r * RS + q] = hi;
            *(uint2*)&pAl[p * TILEH + r * RS + q] = lo;
            split4(sb[h], hi, lo);
            *(uint2*)&pBh[p * TILEH + r * RS + q] = hi;
            *(uint2*)&pBl[p * TILEH + r * RS + q] = lo;
        }
        // prefetch next tile into registers (hidden by this iter's compute)
        if (it + 1 < NIT) {
            int k0 = (it + 1) * 16;
            #pragma unroll
            for (int h = 0; h < 2; h++) {
                sa[h] = *(const float4*)(aptr[h] + k0);
                sb[h] = *(const float4*)(bptr[h] + k0);
            }
        }
        __syncthreads();

        uint32_t bufo = (uint32_t)(p * TILEH * 2);
        uint32_t ah[2][4], al[2][4];
        #pragma unroll
        for (int mt = 0; mt < 2; mt++) {
            ldsm4(ah[mt][0], ah[mt][1], ah[mt][2], ah[mt][3], uAh + bufo + offA[mt]);
            ldsm4(al[mt][0], al[mt][1], al[mt][2], al[mt][3], uAl + bufo + offA[mt]);
        }
        #pragma unroll
        for (int nb = 0; nb < 4; nb++) {
            uint32_t bh0, bh1, bh2, bh3, bl0, bl1, bl2, bl3;
            ldsm4(bh0, bh1, bh2, bh3, uBh + bufo + offB[nb]);
            ldsm4(bl0, bl1, bl2, bl3, uBl + bufo + offB[nb]);
            #pragma unroll
            for (int mt = 0; mt < 2; mt++) {
                mma16(acc[mt][nb * 2],     al[mt], bh0, bh1);
                mma16(acc[mt][nb * 2],     ah[mt], bl0, bl1);
                mma16(acc[mt][nb * 2],     ah[mt], bh0, bh1);
                mma16(acc[mt][nb * 2 + 1], al[mt], bh2, bh3);
                mma16(acc[mt][nb * 2 + 1], ah[mt], bl2, bl3);
                mma16(acc[mt][nb * 2 + 1], ah[mt], bh2, bh3);
            }
        }
        if (it + 1 < NIT) __syncthreads();
    }

    // ---- epilogue (acc: lane g=lane>>2, tg=lane&3; rows g,g+8; cols 2tg,2tg+1)
    int g = lane >> 2, tg = lane & 3;
    if (MODE == 0 || MODE == 1) {
        #pragma unroll
        for (int mt = 0; mt < 2; mt++) {
            #pragma unroll
            for (int half = 0; half < 2; half++) {
                int mr = m0 + m0w + mt * 16 + g + half * 8;
                bool v = (MODE == 0) ? true : (mr < cnt);
                if (v) {
                    long orow = (MODE == 0) ? (long)mr : (long)(base + mr);
                    float* o = C + orow * 512 + jx * 64 + (n0w >> 1) + tg;
                    #pragma unroll
                    for (int nt = 0; nt < 8; nt++) {
                        float gg = acc[mt][nt][half * 2];
                        float uu = acc[mt][nt][half * 2 + 1];
                        o[nt * 4] = (gg / (1.f + expf(-gg))) * uu;
                    }
                }
            }
        }
    } else if (MODE == 2) {
        #pragma unroll
        for (int mt = 0; mt < 2; mt++) {
            #pragma unroll
            for (int half = 0; half < 2; half++) {
                int mr = m0 + m0w + mt * 16 + g + half * 8;
                if (mr < cnt) {
                    int s = base + mr;
                    float* o = C + (long)s * 1024 + jx * 128 + n0w + 2 * tg;
                    #pragma unroll
                    for (int nt = 0; nt < 8; nt++) {
                        o[nt * 8]     = acc[mt][nt][half * 2];
                        o[nt * 8 + 1] = acc[mt][nt][half * 2 + 1];
                    }
                }
            }
        }
    } else {
        #pragma unroll
        for (int mt = 0; mt < 2; mt++) {
            #pragma unroll
            for (int half = 0; half < 2; half++) {
                int mr = m0 + m0w + mt * 16 + g + half * 8;
                float sg = g_shgate[mr];
                float* o = C + (long)mr * 1024 + jx * 128 + n0w + 2 * tg;
                #pragma unroll
                for (int nt = 0; nt < 8; nt++) {
                    o[nt * 8]     = sg * acc[mt][nt][half * 2];
                    o[nt * 8 + 1] = sg * acc[mt][nt][half * 2 + 1];
                }
            }
        }
    }
}

// ---------------- launch ----------------
extern "C" void kernel_launch(void* const* d_in, const int* in_sizes, int n_in,
                              void* d_out, int out_size) {
    const float* x       = (const float*)d_in[0];  // [4096,1024]
    const float* rw      = (const float*)d_in[1];  // [64,1024]
    const float* gate_up = (const float*)d_in[2];  // [64,1024,1024]
    const float* down    = (const float*)d_in[3];  // [64,1024,512]
    const float* shg     = (const float*)d_in[4];  // [512,1024]
    const float* shu     = (const float*)d_in[5];  // [512,1024]
    const float* shd     = (const float*)d_in[6];  // [1024,512]
    const float* sheg    = (const float*)d_in[7];  // [1,1024]

    float* out = (float*)d_out;
    float* probs = nullptr;
    if (out_size >= (int)(TTOK * DHID + TTOK * NEXP))
        probs = out + (size_t)TTOK * DHID;

    float *p_act, *p_acts, *p_logits, *p_y;
    cudaGetSymbolAddress((void**)&p_act, g_act);
    cudaGetSymbolAddress((void**)&p_acts, g_acts);
    cudaGetSymbolAddress((void**)&p_logits, g_logits);
    cudaGetSymbolAddress((void**)&p_y, g_y);

    const int DYN = 8 * TILEH * 2;  // 49152 bytes
    cudaFuncSetAttribute(mma_gemm<0>, cudaFuncAttributeMaxDynamicSharedMemorySize, DYN);
    cudaFuncSetAttribute(mma_gemm<1>, cudaFuncAttributeMaxDynamicSharedMemorySize, DYN);
    cudaFuncSetAttribute(mma_gemm<2>, cudaFuncAttributeMaxDynamicSharedMemorySize, DYN);
    cudaFuncSetAttribute(mma_gemm<3>, cudaFuncAttributeMaxDynamicSharedMemorySize, DYN);

    // 1) router logits (fp32 SIMT — top-k selection is precision-critical)
    logits_gemm<<<dim3(1, TTOK / 64), 256>>>(x, rw, p_logits);
    // 2) softmax + top2 + shared-expert gate
    zero_kernel<<<1, 64>>>();
    softmax_topk_kernel<<<TTOK / 8, 256>>>(x, sheg, probs);
    // 3) group (token, slot) pairs by expert
    scan_kernel<<<1, 32>>>();
    scatter_kernel<<<NPAIR / 256, 256>>>();
    // 4) routed gate_up + fused swiglu -> g_act
    mma_gemm<1><<<dim3(8, 2, NEXP), 256, DYN>>>(x, gate_up, nullptr, p_act);
    // 5) shared gate/up + fused swiglu -> g_acts
    mma_gemm<0><<<dim3(8, TTOK / 128), 256, DYN>>>(x, shg, shu, p_acts);
    // 6) shared down + sigmoid-gate -> out (full overwrite)
    mma_gemm<3><<<dim3(8, TTOK / 128), 256, DYN>>>(p_acts, shd, nullptr, out);
    // 7) routed down -> g_y (plain stores, no atomics)
    mma_gemm<2><<<dim3(8, 2, NEXP), 256, DYN>>>(p_act, down, nullptr, p_y);
    // 8) combine: out += w0*y[s0] + w1*y[s1]
    combine_kernel<<<TTOK / 8, 256>>>(out);
}

// round 8
// speedup vs baseline: 3.0038x; 1.1152x over previous
#include <cuda_runtime.h>
#include <cuda_fp16.h>
#include <math.h>
#include <stdint.h>

#define TTOK 4096
#define DHID 1024
#define NEXP 64
#define IMOE 512
#define NPAIR 8192

// ---------------- scratch (static device globals) ----------------
__device__ int   g_off[NEXP + 1];
__device__ int   g_pe[NPAIR];
__device__ float g_pw[NPAIR];
__device__ int   g_slot_tok[NPAIR];
__device__ int   g_pair_slot[NPAIR];
__device__ float g_shgate[TTOK];
__device__ float g_logits[TTOK * NEXP];
__device__ float g_act[NPAIR * IMOE];        // routed activated   [8192,512]
__device__ float g_acts[TTOK * IMOE];        // shared activated   [4096,512]
__device__ float g_y[NPAIR * DHID];          // routed down output [8192,1024]

// ---------------- helpers ----------------
__device__ __forceinline__ uint32_t smem_u32(const void* p) {
    uint32_t a;
    asm("{ .reg .u64 t; cvta.to.shared.u64 t, %1; cvt.u32.u64 %0, t; }" : "=r"(a) : "l"(p));
    return a;
}
__device__ __forceinline__ void ldsm4(uint32_t& d0, uint32_t& d1, uint32_t& d2, uint32_t& d3,
                                      uint32_t a) {
    asm volatile("ldmatrix.sync.aligned.m8n8.x4.shared.b16 {%0,%1,%2,%3}, [%4];"
                 : "=r"(d0), "=r"(d1), "=r"(d2), "=r"(d3) : "r"(a));
}
// D += A(m16k16 f16) * B(k16n8 f16), fp32 acc
__device__ __forceinline__ void mma16(float* c, const uint32_t* a, uint32_t b0, uint32_t b1) {
    asm volatile(
        "mma.sync.aligned.m16n8k16.row.col.f32.f16.f16.f32 "
        "{%0,%1,%2,%3}, {%4,%5,%6,%7}, {%8,%9}, {%0,%1,%2,%3};"
        : "+f"(c[0]), "+f"(c[1]), "+f"(c[2]), "+f"(c[3])
        : "r"(a[0]), "r"(a[1]), "r"(a[2]), "r"(a[3]), "r"(b0), "r"(b1));
}
__device__ __forceinline__ uint32_t h2u(__half2 h) {
    uint32_t u;
    memcpy(&u, &h, 4);
    return u;
}
// fp16 hi/lo split of 4 floats -> packed f16x2 pairs
__device__ __forceinline__ void split4(float4 v, uint2& hi, uint2& lo) {
    __half2 h01 = __floats2half2_rn(v.x, v.y);
    __half2 h23 = __floats2half2_rn(v.z, v.w);
    float2 f01 = __half22float2(h01);
    float2 f23 = __half22float2(h23);
    __half2 l01 = __floats2half2_rn(v.x - f01.x, v.y - f01.y);
    __half2 l23 = __floats2half2_rn(v.z - f23.x, v.w - f23.y);
    hi = make_uint2(h2u(h01), h2u(h23));
    lo = make_uint2(h2u(l01), h2u(l23));
}
__device__ __forceinline__ uint2 cvt4(float4 v) {
    __half2 h01 = __floats2half2_rn(v.x, v.y);
    __half2 h23 = __floats2half2_rn(v.z, v.w);
    return make_uint2(h2u(h01), h2u(h23));
}
__device__ __forceinline__ int imin(int a, int b) { return a < b ? a : b; }

// ---------------- routing kernels ----------------
__global__ void softmax_topk_kernel(const float* __restrict__ x,
                                    const float* __restrict__ sheg,
                                    float* __restrict__ probs_out) {
    int w = threadIdx.x >> 5, lane = threadIdx.x & 31;
    int t = blockIdx.x * 8 + w;
    if (t >= TTOK) return;

    const float* xr = x + (size_t)t * DHID;
    float sd = 0.f;
    for (int k = lane; k < DHID; k += 32) sd += xr[k] * sheg[k];
    #pragma unroll
    for (int o = 16; o; o >>= 1) sd += __shfl_xor_sync(~0u, sd, o);
    if (lane == 0) g_shgate[t] = 1.f / (1.f + expf(-sd));

    float l0 = g_logits[t * 64 + lane];
    float l1 = g_logits[t * 64 + 32 + lane];
    float m = fmaxf(l0, l1);
    #pragma unroll
    for (int o = 16; o; o >>= 1) m = fmaxf(m, __shfl_xor_sync(~0u, m, o));
    float e0 = expf(l0 - m), e1 = expf(l1 - m);
    float s = e0 + e1;
    #pragma unroll
    for (int o = 16; o; o >>= 1) s += __shfl_xor_sync(~0u, s, o);
    float inv = 1.f / s;
    float p0 = e0 * inv, p1 = e1 * inv;
    if (probs_out) {
        probs_out[t * 64 + lane]      = p0;
        probs_out[t * 64 + 32 + lane] = p1;
    }
    float v0, v1; int i0, i1;
    if (p1 > p0) { v0 = p1; i0 = lane + 32; v1 = p0; i1 = lane; }
    else         { v0 = p0; i0 = lane;      v1 = p1; i1 = lane + 32; }
    #pragma unroll
    for (int o = 16; o; o >>= 1) {
        float w0 = __shfl_xor_sync(~0u, v0, o); int j0 = __shfl_xor_sync(~0u, i0, o);
        float w1 = __shfl_xor_sync(~0u, v1, o); int j1 = __shfl_xor_sync(~0u, i1, o);
        if (w0 > v0 || (w0 == v0 && j0 < i0)) { v1 = v0; i1 = i0; v0 = w0; i0 = j0;
            if (w1 > v1 || (w1 == v1 && j1 < i1)) { v1 = w1; i1 = j1; } }
        else if (w0 > v1 || (w0 == v1 && j0 < i1)) { v1 = w0; i1 = j0; }
    }
    if (lane == 0) {
        float inv2 = 1.f / (v0 + v1 + 1e-9f);
        int p = t * 2;
        g_pe[p] = i0;     g_pw[p] = v0 * inv2;
        g_pe[p + 1] = i1; g_pw[p + 1] = v1 * inv2;
    }
}

// single-block dispatch: histogram -> scan -> scatter slots
__global__ void dispatch_kernel() {
    __shared__ int cnt[NEXP];
    __shared__ int off[NEXP + 1];
    __shared__ int fill[NEXP];
    int tid = threadIdx.x;
    if (tid < NEXP) cnt[tid] = 0;
    __syncthreads();
    for (int p = tid; p < NPAIR; p += 1024) atomicAdd(&cnt[g_pe[p]], 1);
    __syncthreads();
    if (tid == 0) {
        int a = 0;
        for (int e = 0; e < NEXP; e++) { off[e] = a; fill[e] = a; a += cnt[e]; }
        off[NEXP] = a;
    }
    __syncthreads();
    if (tid <= NEXP) g_off[tid] = off[tid];
    for (int p = tid; p < NPAIR; p += 1024) {
        int s = atomicAdd(&fill[g_pe[p]], 1);
        g_slot_tok[s] = p >> 1;
        g_pair_slot[p] = s;
    }
}

// final combine: out[t] += w0*y[slot0] + w1*y[slot1]   (out already holds shared part)
__global__ void combine_kernel(float* __restrict__ out) {
    int w = threadIdx.x >> 5, lane = threadIdx.x & 31;
    int t = blockIdx.x * 8 + w;
    if (t >= TTOK) return;
    int s0 = g_pair_slot[2 * t], s1 = g_pair_slot[2 * t + 1];
    float w0 = g_pw[2 * t], w1 = g_pw[2 * t + 1];
    float4* o = (float4*)(out + (long)t * DHID);
    const float4* y0 = (const float4*)(g_y + (long)s0 * DHID);
    const float4* y1 = (const float4*)(g_y + (long)s1 * DHID);
    for (int i = lane; i < DHID / 4; i += 32) {
        float4 a = o[i], b = y0[i], c = y1[i];
        a.x += w0 * b.x + w1 * c.x;
        a.y += w0 * b.y + w1 * c.y;
        a.z += w0 * b.z + w1 * c.z;
        a.w += w0 * b.w + w1 * c.w;
        o[i] = a;
    }
}

// -------- fp32 SIMT GEMM for router logits (precision-critical), BM=32 BK=32 --------
__global__ void __launch_bounds__(256)
logits_gemm(const float* __restrict__ A, const float* __restrict__ B,
            float* __restrict__ C) {
    const int N = 64, Kd = 1024;
    __shared__ float As[32][33];
    __shared__ float Bs[32][65];
    int tid = threadIdx.x;
    int m0 = blockIdx.y * 32;
    int tx = tid & 15, ty = tid >> 4;

    // A loader: 256 threads x 1 float4 = 32 rows x 32 k
    int ar = tid >> 3, akc = (tid & 7) * 4;
    const float* Arow = A + (long)(m0 + ar) * Kd + akc;
    // B loader: 256 threads x 2 float4 = 64 rows x 32 k
    int br0 = tid >> 3;          // pass 0 rows 0-31
    int bkc = (tid & 7) * 4;
    const float* Brow0 = B + (long)br0 * Kd + bkc;
    const float* Brow1 = B + (long)(br0 + 32) * Kd + bkc;

    float acc[2][4] = {};
    for (int k0 = 0; k0 < Kd; k0 += 32) {
        float4 av = *(const float4*)(Arow + k0);
        float4 bv0 = *(const float4*)(Brow0 + k0);
        float4 bv1 = *(const float4*)(Brow1 + k0);
        As[akc + 0][ar] = av.x; As[akc + 1][ar] = av.y;
        As[akc + 2][ar] = av.z; As[akc + 3][ar] = av.w;
        Bs[bkc + 0][br0] = bv0.x; Bs[bkc + 1][br0] = bv0.y;
        Bs[bkc + 2][br0] = bv0.z; Bs[bkc + 3][br0] = bv0.w;
        Bs[bkc + 0][br0 + 32] = bv1.x; Bs[bkc + 1][br0 + 32] = bv1.y;
        Bs[bkc + 2][br0 + 32] = bv1.z; Bs[bkc + 3][br0 + 32] = bv1.w;
        __syncthreads();
        #pragma unroll 8
        for (int kk = 0; kk < 32; kk++) {
            float a0 = As[kk][ty * 2], a1 = As[kk][ty * 2 + 1];
            #pragma unroll
            for (int j = 0; j < 4; j++) {
                float b = Bs[kk][tx * 4 + j];
                acc[0][j] += a0 * b;
                acc[1][j] += a1 * b;
            }
        }
        __syncthreads();
    }
    #pragma unroll
    for (int i = 0; i < 2; i++)
        #pragma unroll
        for (int j = 0; j < 4; j++)
            C[(long)(m0 + ty * 2 + i) * N + tx * 4 + j] = acc[i][j];
}

// ------- FP16 mma.sync GEMM, CTA 128x128, warp 32x64, BK=16 -------
// TRIPLE modes (0,1): 3xFP16 hi/lo split = fp32-equivalent accuracy.
// Single modes (2,3): plain fp16 RN (unbiased, err ~2.7e-4) — down GEMMs only.
// MODE 0: shared gate/up fused (B rows interleaved even=shg, odd=shu) -> g_acts
// MODE 1: routed gate/up fused (expert=blockIdx.z, A via g_slot_tok) -> g_act
// MODE 2: routed down (A=g_act slots, K=512); plain store to g_y[slot]
// MODE 3: shared down (A=g_acts, K=512); out[m,n] = shgate[m]*v
#define RS 24   // smem row stride in halves (48B): conflict-free for ldmatrix
#define TILEH (128 * RS)  // halves per tile buffer

template <int MODE>
__global__ void __launch_bounds__(256, 2)
mma_gemm(const float* __restrict__ A, const float* __restrict__ B1,
         const float* __restrict__ B2, float* __restrict__ C) {
    constexpr bool TRIPLE = (MODE == 0 || MODE == 1);
    constexpr int Kd  = TRIPLE ? 1024 : 512;
    constexpr int NIT = Kd / 16;

    extern __shared__ __align__(16) __half dynsm[];
    __half* pAh = dynsm;                 // [2][128][RS]
    __half* pAl = dynsm + 2 * TILEH;
    __half* pBh = dynsm + (TRIPLE ? 4 : 2) * TILEH;
    __half* pBl = dynsm + 6 * TILEH;

    int tid = threadIdx.x, lane = tid & 31, wid = tid >> 5;
    int e = blockIdx.z;
    int m0 = blockIdx.y * 128;
    int jx = blockIdx.x;
    int base = 0, cnt = 1 << 30;
    if (MODE == 1 || MODE == 2) {
        base = g_off[e];
        cnt = g_off[e + 1] - base;
        if (m0 >= cnt) return;
    }

    // ---- loader: thread handles rows r0, r0+64; k quad q
    int r0 = tid >> 2, q = (tid & 3) * 4;
    const float* aptr[2];
    const float* bptr[2];
    #pragma unroll
    for (int h = 0; h < 2; h++) {
        int r = r0 + h * 64;
        long ai;
        if (MODE == 1)      { int s = base + imin(m0 + r, cnt - 1); ai = (long)g_slot_tok[s] * 1024; }
        else if (MODE == 2) { int s = base + imin(m0 + r, cnt - 1); ai = (long)s * 512; }
        else                  ai = (long)(m0 + r) * Kd;
        aptr[h] = A + ai + q;

        const float* p;
        if (MODE == 0) {
            int col = jx * 64 + (r >> 1);
            p = ((r & 1) ? B2 : B1) + (long)col * 1024;
        } else if (MODE == 1) {
            int col = jx * 64 + (r >> 1);
            int row = (r & 1) ? (512 + col) : col;
            p = B1 + ((long)e << 20) + (long)row * 1024;
        } else if (MODE == 2) {
            p = B1 + (long)e * (1024 * 512) + (long)(jx * 128 + r) * 512;
        } else {
            p = B1 + (long)(jx * 128 + r) * 512;
        }
        bptr[h] = p + q;
    }

    // ---- ldmatrix lane offsets (bytes within a tile buffer)
    int wm = wid >> 1, wn = wid & 1;
    int m0w = wm * 32, n0w = wn * 64;
    uint32_t offA[2], offB[4];
    #pragma unroll
    for (int mt = 0; mt < 2; mt++) {
        int row = m0w + mt * 16 + ((lane >> 3) & 1) * 8 + (lane & 7);
        int col = ((lane >> 4) & 1) * 8;
        offA[mt] = (uint32_t)((row * RS + col) * 2);
    }
    #pragma unroll
    for (int nb = 0; nb < 4; nb++) {
        int row = n0w + nb * 16 + ((lane >> 4) & 1) * 8 + (lane & 7);
        int col = ((lane >> 3) & 1) * 8;
        offB[nb] = (uint32_t)((row * RS + col) * 2);
    }
    uint32_t uAh = smem_u32(pAh), uAl = smem_u32(pAl);
    uint32_t uBh = smem_u32(pBh), uBl = smem_u32(pBl);

    float acc[2][8][4] = {};

    // prologue: stage tile 0
    float4 sa[2], sb[2];
    #pragma unroll
    for (int h = 0; h < 2; h++) { sa[h] = *(const float4*)aptr[h]; sb[h] = *(const float4*)bptr[h]; }

    for (int it = 0; it < NIT; it++) {
        int p = it & 1;
        // split/convert + STS current staged tile
        #pragma unroll
        for (int h = 0; h < 2; h++) {
            int r = r0 + h * 64;
            if (TRIPLE) {
                uint2 hi, lo;
                split4(sa[h], hi, lo);
                *(uint2*)&pAh[p * TILEH + r * RS + q] = hi;
                *(uint2*)&pAl[p * TILEH + r * RS + q] = lo;
                split4(sb[h], hi, lo);
                *(uint2*)&pBh[p * TILEH + r * RS + q] = hi;
                *(uint2*)&pBl[p * TILEH + r * RS + q] = lo;
            } else {
                *(uint2*)&pAh[p * TILEH + r * RS + q] = cvt4(sa[h]);
                *(uint2*)&pBh[p * TILEH + r * RS + q] = cvt4(sb[h]);
            }
        }
        // prefetch next tile into registers (hidden by this iter's compute)
        if (it + 1 < NIT) {
            int k0 = (it + 1) * 16;
            #pragma unroll
            for (int h = 0; h < 2; h++) {
                sa[h] = *(const float4*)(aptr[h] + k0);
                sb[h] = *(const float4*)(bptr[h] + k0);
            }
        }
        __syncthreads();

        uint32_t bufo = (uint32_t)(p * TILEH * 2);
        uint32_t ah[2][4], al[2][4];
        #pragma unroll
        for (int mt = 0; mt < 2; mt++) {
            ldsm4(ah[mt][0], ah[mt][1], ah[mt][2], ah[mt][3], uAh + bufo + offA[mt]);
            if (TRIPLE)
                ldsm4(al[mt][0], al[mt][1], al[mt][2], al[mt][3], uAl + bufo + offA[mt]);
        }
        #pragma unroll
        for (int nb = 0; nb < 4; nb++) {
            uint32_t bh0, bh1, bh2, bh3;
            ldsm4(bh0, bh1, bh2, bh3, uBh + bufo + offB[nb]);
            if (TRIPLE) {
                uint32_t bl0, bl1, bl2, bl3;
                ldsm4(bl0, bl1, bl2, bl3, uBl + bufo + offB[nb]);
                #pragma unroll
                for (int mt = 0; mt < 2; mt++) {
                    mma16(acc[mt][nb * 2],     al[mt], bh0, bh1);
                    mma16(acc[mt][nb * 2],     ah[mt], bl0, bl1);
                    mma16(acc[mt][nb * 2],     ah[mt], bh0, bh1);
                    mma16(acc[mt][nb * 2 + 1], al[mt], bh2, bh3);
                    mma16(acc[mt][nb * 2 + 1], ah[mt], bl2, bl3);
                    mma16(acc[mt][nb * 2 + 1], ah[mt], bh2, bh3);
                }
            } else {
                #pragma unroll
                for (int mt = 0; mt < 2; mt++) {
                    mma16(acc[mt][nb * 2],     ah[mt], bh0, bh1);
                    mma16(acc[mt][nb * 2 + 1], ah[mt], bh2, bh3);
                }
            }
        }
    }

    // ---- epilogue (acc: lane g=lane>>2, tg=lane&3; rows g,g+8; cols 2tg,2tg+1)
    int g = lane >> 2, tg = lane & 3;
    if (MODE == 0 || MODE == 1) {
        #pragma unroll
        for (int mt = 0; mt < 2; mt++) {
            #pragma unroll
            for (int half = 0; half < 2; half++) {
                int mr = m0 + m0w + mt * 16 + g + half * 8;
                bool v = (MODE == 0) ? true : (mr < cnt);
                if (v) {
                    long orow = (MODE == 0) ? (long)mr : (long)(base + mr);
                    float* o = C + orow * 512 + jx * 64 + (n0w >> 1) + tg;
                    #pragma unroll
                    for (int nt = 0; nt < 8; nt++) {
                        float gg = acc[mt][nt][half * 2];
                        float uu = acc[mt][nt][half * 2 + 1];
                        o[nt * 4] = (gg / (1.f + expf(-gg))) * uu;
                    }
                }
            }
        }
    } else if (MODE == 2) {
        #pragma unroll
        for (int mt = 0; mt < 2; mt++) {
            #pragma unroll
            for (int half = 0; half < 2; half++) {
                int mr = m0 + m0w + mt * 16 + g + half * 8;
                if (mr < cnt) {
                    int s = base + mr;
                    float* o = C + (long)s * 1024 + jx * 128 + n0w + 2 * tg;
                    #pragma unroll
                    for (int nt = 0; nt < 8; nt++) {
                        o[nt * 8]     = acc[mt][nt][half * 2];
                        o[nt * 8 + 1] = acc[mt][nt][half * 2 + 1];
                    }
                }
            }
        }
    } else {
        #pragma unroll
        for (int mt = 0; mt < 2; mt++) {
            #pragma unroll
            for (int half = 0; half < 2; half++) {
                int mr = m0 + m0w + mt * 16 + g + half * 8;
                float sg = g_shgate[mr];
                float* o = C + (long)mr * 1024 + jx * 128 + n0w + 2 * tg;
                #pragma unroll
                for (int nt = 0; nt < 8; nt++) {
                    o[nt * 8]     = sg * acc[mt][nt][half * 2];
                    o[nt * 8 + 1] = sg * acc[mt][nt][half * 2 + 1];
                }
            }
        }
    }
}

// ---------------- launch ----------------
extern "C" void kernel_launch(void* const* d_in, const int* in_sizes, int n_in,
                              void* d_out, int out_size) {
    const float* x       = (const float*)d_in[0];  // [4096,1024]
    const float* rw      = (const float*)d_in[1];  // [64,1024]
    const float* gate_up = (const float*)d_in[2];  // [64,1024,1024]
    const float* down    = (const float*)d_in[3];  // [64,1024,512]
    const float* shg     = (const float*)d_in[4];  // [512,1024]
    const float* shu     = (const float*)d_in[5];  // [512,1024]
    const float* shd     = (const float*)d_in[6];  // [1024,512]
    const float* sheg    = (const float*)d_in[7];  // [1,1024]

    float* out = (float*)d_out;
    float* probs = nullptr;
    if (out_size >= (int)(TTOK * DHID + TTOK * NEXP))
        probs = out + (size_t)TTOK * DHID;

    float *p_act, *p_acts, *p_logits, *p_y;
    cudaGetSymbolAddress((void**)&p_act, g_act);
    cudaGetSymbolAddress((void**)&p_acts, g_acts);
    cudaGetSymbolAddress((void**)&p_logits, g_logits);
    cudaGetSymbolAddress((void**)&p_y, g_y);

    const int DYN3 = 8 * TILEH * 2;  // 49152 bytes (hi+lo, double-buffered)
    const int DYN1 = 4 * TILEH * 2;  // 24576 bytes (hi only)
    cudaFuncSetAttribute(mma_gemm<0>, cudaFuncAttributeMaxDynamicSharedMemorySize, DYN3);
    cudaFuncSetAttribute(mma_gemm<1>, cudaFuncAttributeMaxDynamicSharedMemorySize, DYN3);
    cudaFuncSetAttribute(mma_gemm<2>, cudaFuncAttributeMaxDynamicSharedMemorySize, DYN1);
    cudaFuncSetAttribute(mma_gemm<3>, cudaFuncAttributeMaxDynamicSharedMemorySize, DYN1);

    // 1) router logits (fp32 SIMT — top-k selection is precision-critical)
    logits_gemm<<<dim3(1, TTOK / 32), 256>>>(x, rw, p_logits);
    // 2) softmax + top2 + shared-expert gate
    softmax_topk_kernel<<<TTOK / 8, 256>>>(x, sheg, probs);
    // 3) dispatch: histogram + scan + slot assignment (single block)
    dispatch_kernel<<<1, 1024>>>();
    // 4) shared gate/up + fused swiglu -> g_acts       [profile slot A]
    mma_gemm<0><<<dim3(8, TTOK / 128), 256, DYN3>>>(x, shg, shu, p_acts);
    // 5) routed gate_up + fused swiglu -> g_act
    mma_gemm<1><<<dim3(8, 2, NEXP), 256, DYN3>>>(x, gate_up, nullptr, p_act);
    // 6) shared down + sigmoid-gate -> out (full overwrite)  [profile slot B]
    mma_gemm<3><<<dim3(8, TTOK / 128), 256, DYN1>>>(p_acts, shd, nullptr, out);
    // 7) routed down -> g_y (plain stores, no atomics)
    mma_gemm<2><<<dim3(8, 2, NEXP), 256, DYN1>>>(p_act, down, nullptr, p_y);
    // 8) combine: out += w0*y[s0] + w1*y[s1]
    combine_kernel<<<TTOK / 8, 256>>>(out);
}

// round 9
// speedup vs baseline: 4.1590x; 1.3845x over previous
#include <cuda_runtime.h>
#include <cuda_fp16.h>
#include <math.h>
#include <stdint.h>

#define TTOK 4096
#define DHID 1024
#define NEXP 64
#define IMOE 512
#define NPAIR 8192

// ---------------- scratch (static device globals) ----------------
__device__ int   g_off[NEXP + 1];
__device__ int   g_pe[NPAIR];
__device__ float g_pw[NPAIR];
__device__ int   g_slot_tok[NPAIR];
__device__ int   g_pair_slot[NPAIR];
__device__ float g_shgate[TTOK];
__device__ float g_logits[TTOK * NEXP];
__device__ float g_act[NPAIR * IMOE];        // routed activated   [8192,512]
__device__ float g_acts[TTOK * IMOE];        // shared activated   [4096,512]
__device__ float g_y[NPAIR * DHID];          // routed down output [8192,1024]

// ---------------- helpers ----------------
__device__ __forceinline__ uint32_t smem_u32(const void* p) {
    uint32_t a;
    asm("{ .reg .u64 t; cvta.to.shared.u64 t, %1; cvt.u32.u64 %0, t; }" : "=r"(a) : "l"(p));
    return a;
}
__device__ __forceinline__ void ldsm4(uint32_t& d0, uint32_t& d1, uint32_t& d2, uint32_t& d3,
                                      uint32_t a) {
    asm volatile("ldmatrix.sync.aligned.m8n8.x4.shared.b16 {%0,%1,%2,%3}, [%4];"
                 : "=r"(d0), "=r"(d1), "=r"(d2), "=r"(d3) : "r"(a));
}
// D += A(m16k16 f16) * B(k16n8 f16), fp32 acc
__device__ __forceinline__ void mma16(float* c, const uint32_t* a, uint32_t b0, uint32_t b1) {
    asm volatile(
        "mma.sync.aligned.m16n8k16.row.col.f32.f16.f16.f32 "
        "{%0,%1,%2,%3}, {%4,%5,%6,%7}, {%8,%9}, {%0,%1,%2,%3};"
        : "+f"(c[0]), "+f"(c[1]), "+f"(c[2]), "+f"(c[3])
        : "r"(a[0]), "r"(a[1]), "r"(a[2]), "r"(a[3]), "r"(b0), "r"(b1));
}
__device__ __forceinline__ uint32_t h2u(__half2 h) {
    uint32_t u;
    memcpy(&u, &h, 4);
    return u;
}
// round-to-nearest fp16 convert of 4 floats -> packed f16x2 pair
__device__ __forceinline__ uint2 cvt4(float4 v) {
    __half2 h01 = __floats2half2_rn(v.x, v.y);
    __half2 h23 = __floats2half2_rn(v.z, v.w);
    return make_uint2(h2u(h01), h2u(h23));
}
__device__ __forceinline__ int imin(int a, int b) { return a < b ? a : b; }

// ---------------- routing kernels ----------------
__global__ void softmax_topk_kernel(const float* __restrict__ x,
                                    const float* __restrict__ sheg,
                                    float* __restrict__ probs_out) {
    int w = threadIdx.x >> 5, lane = threadIdx.x & 31;
    int t = blockIdx.x * 8 + w;
    if (t >= TTOK) return;

    const float* xr = x + (size_t)t * DHID;
    float sd = 0.f;
    for (int k = lane; k < DHID; k += 32) sd += xr[k] * sheg[k];
    #pragma unroll
    for (int o = 16; o; o >>= 1) sd += __shfl_xor_sync(~0u, sd, o);
    if (lane == 0) g_shgate[t] = 1.f / (1.f + expf(-sd));

    float l0 = g_logits[t * 64 + lane];
    float l1 = g_logits[t * 64 + 32 + lane];
    float m = fmaxf(l0, l1);
    #pragma unroll
    for (int o = 16; o; o >>= 1) m = fmaxf(m, __shfl_xor_sync(~0u, m, o));
    float e0 = expf(l0 - m), e1 = expf(l1 - m);
    float s = e0 + e1;
    #pragma unroll
    for (int o = 16; o; o >>= 1) s += __shfl_xor_sync(~0u, s, o);
    float inv = 1.f / s;
    float p0 = e0 * inv, p1 = e1 * inv;
    if (probs_out) {
        probs_out[t * 64 + lane]      = p0;
        probs_out[t * 64 + 32 + lane] = p1;
    }
    float v0, v1; int i0, i1;
    if (p1 > p0) { v0 = p1; i0 = lane + 32; v1 = p0; i1 = lane; }
    else         { v0 = p0; i0 = lane;      v1 = p1; i1 = lane + 32; }
    #pragma unroll
    for (int o = 16; o; o >>= 1) {
        float w0 = __shfl_xor_sync(~0u, v0, o); int j0 = __shfl_xor_sync(~0u, i0, o);
        float w1 = __shfl_xor_sync(~0u, v1, o); int j1 = __shfl_xor_sync(~0u, i1, o);
        if (w0 > v0 || (w0 == v0 && j0 < i0)) { v1 = v0; i1 = i0; v0 = w0; i0 = j0;
            if (w1 > v1 || (w1 == v1 && j1 < i1)) { v1 = w1; i1 = j1; } }
        else if (w0 > v1 || (w0 == v1 && j0 < i1)) { v1 = w0; i1 = j0; }
    }
    if (lane == 0) {
        float inv2 = 1.f / (v0 + v1 + 1e-9f);
        int p = t * 2;
        g_pe[p] = i0;     g_pw[p] = v0 * inv2;
        g_pe[p + 1] = i1; g_pw[p + 1] = v1 * inv2;
    }
}

// single-block dispatch: histogram -> scan -> scatter slots
__global__ void dispatch_kernel() {
    __shared__ int cnt[NEXP];
    __shared__ int off[NEXP + 1];
    __shared__ int fill[NEXP];
    int tid = threadIdx.x;
    if (tid < NEXP) cnt[tid] = 0;
    __syncthreads();
    for (int p = tid; p < NPAIR; p += 1024) atomicAdd(&cnt[g_pe[p]], 1);
    __syncthreads();
    if (tid == 0) {
        int a = 0;
        for (int e = 0; e < NEXP; e++) { off[e] = a; fill[e] = a; a += cnt[e]; }
        off[NEXP] = a;
    }
    __syncthreads();
    if (tid <= NEXP) g_off[tid] = off[tid];
    for (int p = tid; p < NPAIR; p += 1024) {
        int s = atomicAdd(&fill[g_pe[p]], 1);
        g_slot_tok[s] = p >> 1;
        g_pair_slot[p] = s;
    }
}

// final combine: out[t] += w0*y[slot0] + w1*y[slot1]   (out already holds shared part)
__global__ void combine_kernel(float* __restrict__ out) {
    int w = threadIdx.x >> 5, lane = threadIdx.x & 31;
    int t = blockIdx.x * 8 + w;
    if (t >= TTOK) return;
    int s0 = g_pair_slot[2 * t], s1 = g_pair_slot[2 * t + 1];
    float w0 = g_pw[2 * t], w1 = g_pw[2 * t + 1];
    float4* o = (float4*)(out + (long)t * DHID);
    const float4* y0 = (const float4*)(g_y + (long)s0 * DHID);
    const float4* y1 = (const float4*)(g_y + (long)s1 * DHID);
    for (int i = lane; i < DHID / 4; i += 32) {
        float4 a = o[i], b = y0[i], c = y1[i];
        a.x += w0 * b.x + w1 * c.x;
        a.y += w0 * b.y + w1 * c.y;
        a.z += w0 * b.z + w1 * c.z;
        a.w += w0 * b.w + w1 * c.w;
        o[i] = a;
    }
}

// -------- fp32 SIMT GEMM for router logits (precision-critical), BM=32 BK=32 --------
__global__ void __launch_bounds__(256)
logits_gemm(const float* __restrict__ A, const float* __restrict__ B,
            float* __restrict__ C) {
    const int N = 64, Kd = 1024;
    __shared__ float As[32][33];
    __shared__ float Bs[32][65];
    int tid = threadIdx.x;
    int m0 = blockIdx.y * 32;
    int tx = tid & 15, ty = tid >> 4;

    int ar = tid >> 3, akc = (tid & 7) * 4;
    const float* Arow = A + (long)(m0 + ar) * Kd + akc;
    int br0 = tid >> 3;
    int bkc = (tid & 7) * 4;
    const float* Brow0 = B + (long)br0 * Kd + bkc;
    const float* Brow1 = B + (long)(br0 + 32) * Kd + bkc;

    float acc[2][4] = {};
    for (int k0 = 0; k0 < Kd; k0 += 32) {
        float4 av = *(const float4*)(Arow + k0);
        float4 bv0 = *(const float4*)(Brow0 + k0);
        float4 bv1 = *(const float4*)(Brow1 + k0);
        As[akc + 0][ar] = av.x; As[akc + 1][ar] = av.y;
        As[akc + 2][ar] = av.z; As[akc + 3][ar] = av.w;
        Bs[bkc + 0][br0] = bv0.x; Bs[bkc + 1][br0] = bv0.y;
        Bs[bkc + 2][br0] = bv0.z; Bs[bkc + 3][br0] = bv0.w;
        Bs[bkc + 0][br0 + 32] = bv1.x; Bs[bkc + 1][br0 + 32] = bv1.y;
        Bs[bkc + 2][br0 + 32] = bv1.z; Bs[bkc + 3][br0 + 32] = bv1.w;
        __syncthreads();
        #pragma unroll 8
        for (int kk = 0; kk < 32; kk++) {
            float a0 = As[kk][ty * 2], a1 = As[kk][ty * 2 + 1];
            #pragma unroll
            for (int j = 0; j < 4; j++) {
                float b = Bs[kk][tx * 4 + j];
                acc[0][j] += a0 * b;
                acc[1][j] += a1 * b;
            }
        }
        __syncthreads();
    }
    #pragma unroll
    for (int i = 0; i < 2; i++)
        #pragma unroll
        for (int j = 0; j < 4; j++)
            C[(long)(m0 + ty * 2 + i) * N + tx * 4 + j] = acc[i][j];
}

// ------- single-pass FP16 mma.sync GEMM, CTA 128x128, warp 32x64, BK=16 -------
// All inputs fp32 -> fp16 RN at load (unbiased; per-GEMM rel err ~3e-4).
// MODE 0: shared gate/up fused (B rows interleaved even=shg, odd=shu) -> g_acts
// MODE 1: routed gate/up fused (expert=blockIdx.z, A via g_slot_tok) -> g_act
// MODE 2: routed down (A=g_act slots, K=512); plain store to g_y[slot]
// MODE 3: shared down (A=g_acts, K=512); out[m,n] = shgate[m]*v
#define RS 24   // smem row stride in halves (48B): conflict-free for ldmatrix
#define TILEH (128 * RS)  // halves per tile buffer

template <int MODE>
__global__ void __launch_bounds__(256, 2)
mma_gemm(const float* __restrict__ A, const float* __restrict__ B1,
         const float* __restrict__ B2, float* __restrict__ C) {
    constexpr int Kd  = (MODE == 0 || MODE == 1) ? 1024 : 512;
    constexpr int NIT = Kd / 16;

    extern __shared__ __align__(16) __half dynsm[];
    __half* pAh = dynsm;                 // [2][128][RS]
    __half* pBh = dynsm + 2 * TILEH;

    int tid = threadIdx.x, lane = tid & 31, wid = tid >> 5;
    int e = blockIdx.z;
    int m0 = blockIdx.y * 128;
    int jx = blockIdx.x;
    int base = 0, cnt = 1 << 30;
    if (MODE == 1 || MODE == 2) {
        base = g_off[e];
        cnt = g_off[e + 1] - base;
        if (m0 >= cnt) return;
    }

    // ---- loader: thread handles rows r0, r0+64; k quad q
    int r0 = tid >> 2, q = (tid & 3) * 4;
    const float* aptr[2];
    const float* bptr[2];
    #pragma unroll
    for (int h = 0; h < 2; h++) {
        int r = r0 + h * 64;
        long ai;
        if (MODE == 1)      { int s = base + imin(m0 + r, cnt - 1); ai = (long)g_slot_tok[s] * 1024; }
        else if (MODE == 2) { int s = base + imin(m0 + r, cnt - 1); ai = (long)s * 512; }
        else                  ai = (long)(m0 + r) * Kd;
        aptr[h] = A + ai + q;

        const float* p;
        if (MODE == 0) {
            int col = jx * 64 + (r >> 1);
            p = ((r & 1) ? B2 : B1) + (long)col * 1024;
        } else if (MODE == 1) {
            int col = jx * 64 + (r >> 1);
            int row = (r & 1) ? (512 + col) : col;
            p = B1 + ((long)e << 20) + (long)row * 1024;
        } else if (MODE == 2) {
            p = B1 + (long)e * (1024 * 512) + (long)(jx * 128 + r) * 512;
        } else {
            p = B1 + (long)(jx * 128 + r) * 512;
        }
        bptr[h] = p + q;
    }

    // ---- ldmatrix lane offsets (bytes within a tile buffer)
    int wm = wid >> 1, wn = wid & 1;
    int m0w = wm * 32, n0w = wn * 64;
    uint32_t offA[2], offB[4];
    #pragma unroll
    for (int mt = 0; mt < 2; mt++) {
        int row = m0w + mt * 16 + ((lane >> 3) & 1) * 8 + (lane & 7);
        int col = ((lane >> 4) & 1) * 8;
        offA[mt] = (uint32_t)((row * RS + col) * 2);
    }
    #pragma unroll
    for (int nb = 0; nb < 4; nb++) {
        int row = n0w + nb * 16 + ((lane >> 4) & 1) * 8 + (lane & 7);
        int col = ((lane >> 3) & 1) * 8;
        offB[nb] = (uint32_t)((row * RS + col) * 2);
    }
    uint32_t uAh = smem_u32(pAh), uBh = smem_u32(pBh);

    float acc[2][8][4] = {};

    // prologue: stage tile 0
    float4 sa[2], sb[2];
    #pragma unroll
    for (int h = 0; h < 2; h++) { sa[h] = *(const float4*)aptr[h]; sb[h] = *(const float4*)bptr[h]; }

    for (int it = 0; it < NIT; it++) {
        int p = it & 1;
        // convert + STS current staged tile
        #pragma unroll
        for (int h = 0; h < 2; h++) {
            int r = r0 + h * 64;
            *(uint2*)&pAh[p * TILEH + r * RS + q] = cvt4(sa[h]);
            *(uint2*)&pBh[p * TILEH + r * RS + q] = cvt4(sb[h]);
        }
        // prefetch next tile into registers (hidden by this iter's compute)
        if (it + 1 < NIT) {
            int k0 = (it + 1) * 16;
            #pragma unroll
            for (int h = 0; h < 2; h++) {
                sa[h] = *(const float4*)(aptr[h] + k0);
                sb[h] = *(const float4*)(bptr[h] + k0);
            }
        }
        __syncthreads();

        uint32_t bufo = (uint32_t)(p * TILEH * 2);
        uint32_t ah[2][4];
        #pragma unroll
        for (int mt = 0; mt < 2; mt++)
            ldsm4(ah[mt][0], ah[mt][1], ah[mt][2], ah[mt][3], uAh + bufo + offA[mt]);
        #pragma unroll
        for (int nb = 0; nb < 4; nb++) {
            uint32_t bh0, bh1, bh2, bh3;
            ldsm4(bh0, bh1, bh2, bh3, uBh + bufo + offB[nb]);
            #pragma unroll
            for (int mt = 0; mt < 2; mt++) {
                mma16(acc[mt][nb * 2],     ah[mt], bh0, bh1);
                mma16(acc[mt][nb * 2 + 1], ah[mt], bh2, bh3);
            }
        }
    }

    // ---- epilogue (acc: lane g=lane>>2, tg=lane&3; rows g,g+8; cols 2tg,2tg+1)
    int g = lane >> 2, tg = lane & 3;
    if (MODE == 0 || MODE == 1) {
        #pragma unroll
        for (int mt = 0; mt < 2; mt++) {
            #pragma unroll
            for (int half = 0; half < 2; half++) {
                int mr = m0 + m0w + mt * 16 + g + half * 8;
                bool v = (MODE == 0) ? true : (mr < cnt);
                if (v) {
                    long orow = (MODE == 0) ? (long)mr : (long)(base + mr);
                    float* o = C + orow * 512 + jx * 64 + (n0w >> 1) + tg;
                    #pragma unroll
                    for (int nt = 0; nt < 8; nt++) {
                        float gg = acc[mt][nt][half * 2];
                        float uu = acc[mt][nt][half * 2 + 1];
                        o[nt * 4] = (gg / (1.f + expf(-gg))) * uu;
                    }
                }
            }
        }
    } else if (MODE == 2) {
        #pragma unroll
        for (int mt = 0; mt < 2; mt++) {
            #pragma unroll
            for (int half = 0; half < 2; half++) {
                int mr = m0 + m0w + mt * 16 + g + half * 8;
                if (mr < cnt) {
                    int s = base + mr;
                    float* o = C + (long)s * 1024 + jx * 128 + n0w + 2 * tg;
                    #pragma unroll
                    for (int nt = 0; nt < 8; nt++) {
                        o[nt * 8]     = acc[mt][nt][half * 2];
                        o[nt * 8 + 1] = acc[mt][nt][half * 2 + 1];
                    }
                }
            }
        }
    } else {
        #pragma unroll
        for (int mt = 0; mt < 2; mt++) {
            #pragma unroll
            for (int half = 0; half < 2; half++) {
                int mr = m0 + m0w + mt * 16 + g + half * 8;
                float sg = g_shgate[mr];
                float* o = C + (long)mr * 1024 + jx * 128 + n0w + 2 * tg;
                #pragma unroll
                for (int nt = 0; nt < 8; nt++) {
                    o[nt * 8]     = sg * acc[mt][nt][half * 2];
                    o[nt * 8 + 1] = sg * acc[mt][nt][half * 2 + 1];
                }
            }
        }
    }
}

// ---------------- launch ----------------
extern "C" void kernel_launch(void* const* d_in, const int* in_sizes, int n_in,
                              void* d_out, int out_size) {
    const float* x       = (const float*)d_in[0];  // [4096,1024]
    const float* rw      = (const float*)d_in[1];  // [64,1024]
    const float* gate_up = (const float*)d_in[2];  // [64,1024,1024]
    const float* down    = (const float*)d_in[3];  // [64,1024,512]
    const float* shg     = (const float*)d_in[4];  // [512,1024]
    const float* shu     = (const float*)d_in[5];  // [512,1024]
    const float* shd     = (const float*)d_in[6];  // [1024,512]
    const float* sheg    = (const float*)d_in[7];  // [1,1024]

    float* out = (float*)d_out;
    float* probs = nullptr;
    if (out_size >= (int)(TTOK * DHID + TTOK * NEXP))
        probs = out + (size_t)TTOK * DHID;

    float *p_act, *p_acts, *p_logits, *p_y;
    cudaGetSymbolAddress((void**)&p_act, g_act);
    cudaGetSymbolAddress((void**)&p_acts, g_acts);
    cudaGetSymbolAddress((void**)&p_logits, g_logits);
    cudaGetSymbolAddress((void**)&p_y, g_y);

    const int DYN = 4 * TILEH * 2;  // 24576 bytes (hi only, double-buffered)
    cudaFuncSetAttribute(mma_gemm<0>, cudaFuncAttributeMaxDynamicSharedMemorySize, DYN);
    cudaFuncSetAttribute(mma_gemm<1>, cudaFuncAttributeMaxDynamicSharedMemorySize, DYN);
    cudaFuncSetAttribute(mma_gemm<2>, cudaFuncAttributeMaxDynamicSharedMemorySize, DYN);
    cudaFuncSetAttribute(mma_gemm<3>, cudaFuncAttributeMaxDynamicSharedMemorySize, DYN);

    // 1) router logits (fp32 SIMT — top-k selection is precision-critical)
    logits_gemm<<<dim3(1, TTOK / 32), 256>>>(x, rw, p_logits);
    // 2) softmax + top2 + shared-expert gate
    softmax_topk_kernel<<<TTOK / 8, 256>>>(x, sheg, probs);
    // 3) dispatch: histogram + scan + slot assignment (single block)
    dispatch_kernel<<<1, 1024>>>();
    // 4) shared gate/up + fused swiglu -> g_acts       [profile slot A]
    mma_gemm<0><<<dim3(8, TTOK / 128), 256, DYN>>>(x, shg, shu, p_acts);
    // 5) routed gate_up + fused swiglu -> g_act
    mma_gemm<1><<<dim3(8, 2, NEXP), 256, DYN>>>(x, gate_up, nullptr, p_act);
    // 6) shared down + sigmoid-gate -> out (full overwrite)
    mma_gemm<3><<<dim3(8, TTOK / 128), 256, DYN>>>(p_acts, shd, nullptr, out);
    // 7) routed down -> g_y (plain stores, no atomics)
    mma_gemm<2><<<dim3(8, 2, NEXP), 256, DYN>>>(p_act, down, nullptr, p_y);
    // 8) combine: out += w0*y[s0] + w1*y[s1]
    combine_kernel<<<TTOK / 8, 256>>>(out);
}